// round 14
// baseline (speedup 1.0000x reference)
#include <cuda_runtime.h>
#include <cstdint>

// ---------------------------------------------------------------------------
// GraphSAGE VGAE encoder, GB300.  Round 14: register-tiled GEMMs.
//  * edge_index dtype (int32 vs int64) sniffed at runtime  (R13 fix - KEEP)
//  * scratch resolved in-kernel via id switch              (R13 fix - KEEP)
// Dataflow (project-then-aggregate; aggregation is linear):
//   z1 = x @ Wl1               agg1 = mean-gather(z1)
//   h1 = relu(x @ Wr1 + agg1 + b1)
//   z2 = h1 @ Wl2              agg2 = mean-gather(z2)
//   h2 = relu(h1 @ Wr2 + agg2 + b2)
//   agg3 = mean-gather(h2)     (shared by both heads)
//   mu = agg3 @ Wlmu + h2 @ Wrmu + bmu
//   lv = agg3 @ Wllv + h2 @ Wrlv + blv
// ---------------------------------------------------------------------------

static constexpr int NODES = 50000;
static constexpr int ED    = 800000;
static constexpr int IN_D  = 128;
static constexpr int D1    = 117;
static constexpr int D2    = 42;
static constexpr int DOUT  = 24;

static constexpr int SCAN_B = 256;
static constexpr int NBLK   = (NODES + SCAN_B - 1) / SCAN_B;   // 196

__device__ float g_z1  [NODES * D1];
__device__ float g_agg1[NODES * D1];
__device__ float g_h1  [NODES * D1];
__device__ float g_z2  [NODES * D2];
__device__ float g_agg2[NODES * D2];
__device__ float g_h2  [NODES * D2];
__device__ float g_agg3[NODES * D2];
__device__ float g_invdeg[NODES];
__device__ int   g_is64;
__device__ int   g_deg[NODES];
__device__ int   g_row_ptr[NODES + 1];
__device__ int   g_blocksum[NBLK];
__device__ int   g_blockoff[NBLK];
__device__ int   g_cursor[NODES];
__device__ int   g_csr_src[ED];

// scratch buffer selector — device-side only (no host symbol addresses)
__device__ __forceinline__ float* scratch(int id) {
    switch (id) {
        case 0: return g_z1;
        case 1: return g_agg1;
        case 2: return g_h1;
        case 3: return g_z2;
        case 4: return g_agg2;
        case 5: return g_h2;
        case 6: return g_agg3;
    }
    return nullptr;
}

// ---------------------------------------------------------------------------
// Detect edge_index dtype. int64 little-endian: high 32-bit words are 0
// (values < 50000). int32: odd words are other indices, ~never 0.
__global__ void sniff_kernel(const void* __restrict__ ei) {
    if (threadIdx.x != 0 || blockIdx.x != 0) return;
    const unsigned* w = (const unsigned*)ei;
    int zeros = 0;
    for (int i = 0; i < 256; i++) zeros += (w[2 * i + 1] == 0u) ? 1 : 0;
    g_is64 = (zeros >= 128) ? 1 : 0;
}

__global__ void init_kernel() {
    int i = blockIdx.x * blockDim.x + threadIdx.x;
    if (i < NODES) g_deg[i] = 0;
}

__device__ __forceinline__ void decode_edge(const void* ei, int e, int& s, int& d) {
    if (g_is64) {
        const long long* p = (const long long*)ei;
        s = (int)p[e];
        d = (int)p[ED + e];
    } else {
        const int* p = (const int*)ei;
        s = p[e];
        d = p[ED + e];
    }
    s = min(max(s, 0), NODES - 1);
    d = min(max(d, 0), NODES - 1);
}

// count in-degrees (dst only)
__global__ void edge_count_kernel(const void* __restrict__ ei) {
    int e = blockIdx.x * blockDim.x + threadIdx.x;
    if (e >= ED) return;
    int s, d;
    decode_edge(ei, e, s, d);
    atomicAdd(&g_deg[d], 1);
}

// per-block exclusive scan of degrees; emit block totals
__global__ void scan_local_kernel() {
    __shared__ int sm[SCAN_B];
    int tid = threadIdx.x;
    int i = blockIdx.x * SCAN_B + tid;
    int v = (i < NODES) ? g_deg[i] : 0;
    sm[tid] = v;
    __syncthreads();
    for (int off = 1; off < SCAN_B; off <<= 1) {
        int t = (tid >= off) ? sm[tid - off] : 0;
        __syncthreads();
        sm[tid] += t;
        __syncthreads();
    }
    if (i < NODES) g_row_ptr[i] = sm[tid] - v;        // local exclusive
    if (tid == SCAN_B - 1) g_blocksum[blockIdx.x] = sm[tid];
}

__global__ void scan_blocksums_kernel() {
    __shared__ int sm[SCAN_B];
    int tid = threadIdx.x;
    int v = (tid < NBLK) ? g_blocksum[tid] : 0;
    sm[tid] = v;
    __syncthreads();
    for (int off = 1; off < SCAN_B; off <<= 1) {
        int t = (tid >= off) ? sm[tid - off] : 0;
        __syncthreads();
        sm[tid] += t;
        __syncthreads();
    }
    if (tid < NBLK) g_blockoff[tid] = sm[tid] - v;    // exclusive
}

__global__ void scan_add_kernel() {
    int i = blockIdx.x * blockDim.x + threadIdx.x;
    if (i >= NODES) return;
    int rp = g_row_ptr[i] + g_blockoff[i / SCAN_B];
    g_row_ptr[i] = rp;
    g_cursor[i]  = rp;
    g_invdeg[i]  = 1.0f / fmaxf((float)g_deg[i], 1.0f);
    if (i == 0) g_row_ptr[NODES] = ED;
}

// scatter src ids into CSR slots (decode ei inline; int atomics)
__global__ void scatter_kernel(const void* __restrict__ ei) {
    int e = blockIdx.x * blockDim.x + threadIdx.x;
    if (e >= ED) return;
    int s, d;
    decode_edge(ei, e, s, d);
    int pos = atomicAdd(&g_cursor[d], 1);
    g_csr_src[pos] = s;
}

// ---------------------------------------------------------------------------
// Mean-gather, NPB nodes per 128-thread block. Lane j accumulates column j.
// Dual accumulators for 2 outstanding loads.
template<int NPB>
__global__ void gather_kernel(int src_id, int dst_id, int D) {
    const float* __restrict__ Z   = scratch(src_id);
    float*       __restrict__ AGG = scratch(dst_id);
    constexpr int LANES = 128 / NPB;
    int sub = threadIdx.x / LANES;
    int j   = threadIdx.x - sub * LANES;
    int n   = blockIdx.x * NPB + sub;
    if (n >= NODES || j >= D) return;
    int beg = g_row_ptr[n];
    int end = g_row_ptr[n + 1];
    float acc0 = 0.0f, acc1 = 0.0f;
    int i = beg;
    for (; i + 1 < end; i += 2) {
        int s0 = g_csr_src[i];
        int s1 = g_csr_src[i + 1];
        acc0 += Z[(size_t)s0 * D + j];
        acc1 += Z[(size_t)s1 * D + j];
    }
    if (i < end) acc0 += Z[(size_t)g_csr_src[i] * D + j];
    AGG[(size_t)n * D + j] = (acc0 + acc1) * g_invdeg[n];
}

// ---------------------------------------------------------------------------
// Register-tiled fused linear.
//   out[n,j] = act( (A1@W1)[n,j] + (A2@W2)[n,j] + C[n,j] + bias[j] )
// 256 threads, 64 rows/block. Thread (tx,ty): tx=col lane (32), ty=row group
// (8); each thread owns 8 rows x NC cols. A rows staged in smem (broadcast
// reads); W from global (L1-resident, coalesced across tx).
// Per k: 8 LDS + NC LDG + 8*NC FMA  ->  ~1.37 instr/MAC at NC=4.
template<int K1, int K2, int NC>
__global__ void lin_kernel(const float* __restrict__ a1_ext, int a1_id,
                           const float* __restrict__ W1,
                           int a2_id, const float* __restrict__ W2,
                           int c_id,
                           const float* __restrict__ bias, int has_bias,
                           float* __restrict__ oext, int out_id,
                           int DO, int relu, int N)
{
    __shared__ float sA1[64 * K1];
    __shared__ float sA2[(K2 > 0 ? 64 * K2 : 1)];

    const float* __restrict__ A1 = (a1_id >= 0) ? scratch(a1_id) : a1_ext;
    const float* __restrict__ C  = (c_id  >= 0) ? scratch(c_id)  : nullptr;
    float* __restrict__ out = (out_id >= 0) ? scratch(out_id) : oext;

    const int tid = threadIdx.x;
    const int n0  = blockIdx.x * 64;

    // stage A tiles (coalesced; edge rows clamped)
    for (int i = tid; i < 64 * K1; i += 256) {
        int r = i / K1, k = i - r * K1;
        int row = min(n0 + r, N - 1);
        sA1[i] = A1[(size_t)row * K1 + k];
    }
    if constexpr (K2 > 0) {
        const float* __restrict__ A2 = scratch(a2_id);
        for (int i = tid; i < 64 * K2; i += 256) {
            int r = i / K2, k = i - r * K2;
            int row = min(n0 + r, N - 1);
            sA2[i] = A2[(size_t)row * K2 + k];
        }
    }
    __syncthreads();

    const int tx = tid & 31;
    const int ty = tid >> 5;            // 0..7, rows ty*8 .. ty*8+7

    float acc[8][NC];
    #pragma unroll
    for (int r = 0; r < 8; r++)
        #pragma unroll
        for (int c = 0; c < NC; c++) acc[r][c] = 0.0f;

    #pragma unroll 4
    for (int k = 0; k < K1; k++) {
        float w[NC];
        #pragma unroll
        for (int c = 0; c < NC; c++) {
            int j = tx + 32 * c;
            w[c] = (j < DO) ? W1[k * DO + j] : 0.0f;
        }
        #pragma unroll
        for (int r = 0; r < 8; r++) {
            float a = sA1[(ty * 8 + r) * K1 + k];
            #pragma unroll
            for (int c = 0; c < NC; c++) acc[r][c] += a * w[c];
        }
    }
    if constexpr (K2 > 0) {
        #pragma unroll 4
        for (int k = 0; k < K2; k++) {
            float w[NC];
            #pragma unroll
            for (int c = 0; c < NC; c++) {
                int j = tx + 32 * c;
                w[c] = (j < DO) ? W2[k * DO + j] : 0.0f;
            }
            #pragma unroll
            for (int r = 0; r < 8; r++) {
                float a = sA2[(ty * 8 + r) * K2 + k];
                #pragma unroll
                for (int c = 0; c < NC; c++) acc[r][c] += a * w[c];
            }
        }
    }

    // epilogue
    #pragma unroll
    for (int r = 0; r < 8; r++) {
        int row = n0 + ty * 8 + r;
        if (row >= N) continue;
        #pragma unroll
        for (int c = 0; c < NC; c++) {
            int j = tx + 32 * c;
            if (j >= DO) continue;
            float v = acc[r][c];
            if (has_bias) v += bias[j];
            if (C) v += C[(size_t)row * DO + j];
            if (relu) v = fmaxf(v, 0.0f);
            out[(size_t)row * DO + j] = v;
        }
    }
}

// ---------------------------------------------------------------------------
extern "C" void kernel_launch(void* const* d_in, const int* in_sizes, int n_in,
                              void* d_out, int out_size) {
    const float* x    = (const float*)d_in[0];
    const void*  ei   = (const void*)d_in[1];
    const float* Wl1  = (const float*)d_in[2];
    const float* Wr1  = (const float*)d_in[3];
    const float* b1   = (const float*)d_in[4];
    const float* Wl2  = (const float*)d_in[5];
    const float* Wr2  = (const float*)d_in[6];
    const float* b2   = (const float*)d_in[7];
    const float* Wlmu = (const float*)d_in[8];
    const float* Wrmu = (const float*)d_in[9];
    const float* bmu  = (const float*)d_in[10];
    const float* Wllv = (const float*)d_in[11];
    const float* Wrlv = (const float*)d_in[12];
    const float* blv  = (const float*)d_in[13];
    float* out = (float*)d_out;

    const int NB    = (NODES + 255) / 256;
    const int EB    = (ED + 255) / 256;
    const int LGRID = (NODES + 63) / 64;       // 782

    // ---- CSR build ----
    sniff_kernel<<<1, 32>>>(ei);
    init_kernel<<<NB, 256>>>();
    edge_count_kernel<<<EB, 256>>>(ei);
    scan_local_kernel<<<NBLK, SCAN_B>>>();
    scan_blocksums_kernel<<<1, SCAN_B>>>();
    scan_add_kernel<<<NB, 256>>>();
    scatter_kernel<<<EB, 256>>>(ei);

    // z1 = x @ Wl1                         -> scratch 0
    lin_kernel<IN_D, 0, 4><<<LGRID, 256>>>(x, -1, Wl1,
                                           -1, nullptr, -1,
                                           nullptr, 0, nullptr, 0,
                                           D1, 0, NODES);

    // agg1 = mean-gather(z1)                0 -> 1
    gather_kernel<1><<<NODES, 128>>>(0, 1, D1);

    // h1 = relu(x @ Wr1 + agg1 + b1)       -> scratch 2
    lin_kernel<IN_D, 0, 4><<<LGRID, 256>>>(x, -1, Wr1,
                                           -1, nullptr, 1,
                                           b1, 1, nullptr, 2,
                                           D1, 1, NODES);

    // z2 = h1 @ Wl2                        -> scratch 3
    lin_kernel<D1, 0, 2><<<LGRID, 256>>>(nullptr, 2, Wl2,
                                         -1, nullptr, -1,
                                         nullptr, 0, nullptr, 3,
                                         D2, 0, NODES);

    // agg2 = mean-gather(z2)                3 -> 4
    gather_kernel<2><<<(NODES + 1) / 2, 128>>>(3, 4, D2);

    // h2 = relu(h1 @ Wr2 + agg2 + b2)      -> scratch 5
    lin_kernel<D1, 0, 2><<<LGRID, 256>>>(nullptr, 2, Wr2,
                                         -1, nullptr, 4,
                                         b2, 1, nullptr, 5,
                                         D2, 1, NODES);

    // agg3 = mean-gather(h2)                5 -> 6
    gather_kernel<2><<<(NODES + 1) / 2, 128>>>(5, 6, D2);

    // mu = agg3 @ Wlmu + h2 @ Wrmu + bmu   -> out[0..]
    lin_kernel<D2, D2, 1><<<LGRID, 256>>>(nullptr, 6, Wlmu,
                                          5, Wrmu, -1,
                                          bmu, 1, out, -1,
                                          DOUT, 0, NODES);

    // lv = agg3 @ Wllv + h2 @ Wrlv + blv   -> out[NODES*DOUT..]
    lin_kernel<D2, D2, 1><<<LGRID, 256>>>(nullptr, 6, Wllv,
                                          5, Wrlv, -1,
                                          blv, 1, out + (size_t)NODES * DOUT, -1,
                                          DOUT, 0, NODES);
}

// round 15
// speedup vs baseline: 1.3493x; 1.3493x over previous
#include <cuda_runtime.h>
#include <cstdint>

// ---------------------------------------------------------------------------
// GraphSAGE VGAE encoder, GB300.  R15: R13 lin structure + shared-A fusion.
//  * edge_index dtype sniffed at runtime (int32 vs int64)   [R13 fix]
//  * scratch resolved in-kernel via id switch               [R13 fix]
//  * GEMM pairs sharing A fused (2 outputs per pass, 1.75 instr/MAC)
//  * big layer-1 GEMM hoisted to launch index 5 for ncu capture
// Dataflow:
//   (z1, xw1) = x @ (Wl1, Wr1)         agg1 = mean-gather(z1)
//   h1 = relu(xw1 + agg1)              (b1 folded into xw1)
//   (z2, hw2) = h1 @ (Wl2, Wr2)        agg2 = mean-gather(z2)
//   h2 = relu(hw2 + agg2)              (b2 folded into hw2)
//   agg3 = mean-gather(h2)
//   mu = agg3 @ Wlmu + h2 @ Wrmu + bmu ; lv likewise        (one kernel)
// ---------------------------------------------------------------------------

static constexpr int NODES = 50000;
static constexpr int ED    = 800000;
static constexpr int IN_D  = 128;
static constexpr int D1    = 117;
static constexpr int D2    = 42;
static constexpr int DOUT  = 24;

static constexpr int SCAN_B = 256;
static constexpr int NBLK   = (NODES + SCAN_B - 1) / SCAN_B;   // 196

__device__ float g_z1  [NODES * D1];   // id 0
__device__ float g_agg1[NODES * D1];   // id 1
__device__ float g_h1  [NODES * D1];   // id 2  (holds xw1, then h1 in place)
__device__ float g_z2  [NODES * D2];   // id 3
__device__ float g_agg2[NODES * D2];   // id 4
__device__ float g_h2  [NODES * D2];   // id 5  (holds hw2, then h2 in place)
__device__ float g_agg3[NODES * D2];   // id 6
__device__ float g_invdeg[NODES];
__device__ int   g_is64;
__device__ int   g_src[ED];
__device__ int   g_dst[ED];
__device__ int   g_deg[NODES];
__device__ int   g_row_ptr[NODES + 1];
__device__ int   g_blocksum[NBLK];
__device__ int   g_blockoff[NBLK];
__device__ int   g_cursor[NODES];
__device__ int   g_csr_src[ED];

__device__ __forceinline__ float* scratch(int id) {
    switch (id) {
        case 0: return g_z1;
        case 1: return g_agg1;
        case 2: return g_h1;
        case 3: return g_z2;
        case 4: return g_agg2;
        case 5: return g_h2;
        case 6: return g_agg3;
    }
    return nullptr;
}

// ---------------------------------------------------------------------------
// Detect edge_index dtype (int64: high words are 0 since ids < 50000).
__global__ void sniff_kernel(const void* __restrict__ ei) {
    if (threadIdx.x != 0 || blockIdx.x != 0) return;
    const unsigned* w = (const unsigned*)ei;
    int zeros = 0;
    for (int i = 0; i < 256; i++) zeros += (w[2 * i + 1] == 0u) ? 1 : 0;
    g_is64 = (zeros >= 128) ? 1 : 0;
}

__global__ void init_kernel() {
    int i = blockIdx.x * blockDim.x + threadIdx.x;
    if (i < NODES) g_deg[i] = 0;
}

// decode edges -> g_src/g_dst, count in-degrees
__global__ void edge_prep_kernel(const void* __restrict__ ei) {
    int e = blockIdx.x * blockDim.x + threadIdx.x;
    if (e >= ED) return;
    int s, d;
    if (g_is64) {
        const long long* p = (const long long*)ei;
        s = (int)p[e];
        d = (int)p[ED + e];
    } else {
        const int* p = (const int*)ei;
        s = p[e];
        d = p[ED + e];
    }
    s = min(max(s, 0), NODES - 1);
    d = min(max(d, 0), NODES - 1);
    g_src[e] = s;
    g_dst[e] = d;
    atomicAdd(&g_deg[d], 1);
}

__global__ void scan_local_kernel() {
    __shared__ int sm[SCAN_B];
    int tid = threadIdx.x;
    int i = blockIdx.x * SCAN_B + tid;
    int v = (i < NODES) ? g_deg[i] : 0;
    sm[tid] = v;
    __syncthreads();
    for (int off = 1; off < SCAN_B; off <<= 1) {
        int t = (tid >= off) ? sm[tid - off] : 0;
        __syncthreads();
        sm[tid] += t;
        __syncthreads();
    }
    if (i < NODES) g_row_ptr[i] = sm[tid] - v;
    if (tid == SCAN_B - 1) g_blocksum[blockIdx.x] = sm[tid];
}

__global__ void scan_blocksums_kernel() {
    __shared__ int sm[SCAN_B];
    int tid = threadIdx.x;
    int v = (tid < NBLK) ? g_blocksum[tid] : 0;
    sm[tid] = v;
    __syncthreads();
    for (int off = 1; off < SCAN_B; off <<= 1) {
        int t = (tid >= off) ? sm[tid - off] : 0;
        __syncthreads();
        sm[tid] += t;
        __syncthreads();
    }
    if (tid < NBLK) g_blockoff[tid] = sm[tid] - v;
}

__global__ void scan_add_kernel() {
    int i = blockIdx.x * blockDim.x + threadIdx.x;
    if (i >= NODES) return;
    int rp = g_row_ptr[i] + g_blockoff[i / SCAN_B];
    g_row_ptr[i] = rp;
    g_cursor[i]  = rp;
    g_invdeg[i]  = 1.0f / fmaxf((float)g_deg[i], 1.0f);
    if (i == 0) g_row_ptr[NODES] = ED;
}

__global__ void scatter_kernel() {
    int e = blockIdx.x * blockDim.x + threadIdx.x;
    if (e >= ED) return;
    int pos = atomicAdd(&g_cursor[g_dst[e]], 1);
    g_csr_src[pos] = g_src[e];
}

// ---------------------------------------------------------------------------
// Mean-gather (R13-proven): one block per node, lane j = column.
__global__ void gather_kernel(int src_id, int dst_id, int D) {
    const float* __restrict__ Z   = scratch(src_id);
    float*       __restrict__ AGG = scratch(dst_id);
    int n = blockIdx.x;
    int j = threadIdx.x;
    if (j >= D) return;
    int beg = g_row_ptr[n];
    int end = g_row_ptr[n + 1];
    float acc = 0.0f;
    for (int i = beg; i < end; i++) {
        int s = g_csr_src[i];
        acc += Z[(size_t)s * D + j];
    }
    AGG[(size_t)n * D + j] = acc * g_invdeg[n];
}

// elementwise: H[i] = relu(H[i] + AGG[i])   (bias already folded into H)
__global__ void add_relu_kernel(int h_id, int agg_id, int total) {
    float* __restrict__ H   = scratch(h_id);
    const float* __restrict__ A = scratch(agg_id);
    int i = blockIdx.x * blockDim.x + threadIdx.x;
    if (i < total) H[i] = fmaxf(H[i] + A[i], 0.0f);
}

// ---------------------------------------------------------------------------
// Fused dual-output linear (R13 structure): 4 rows/block, thread j = column.
//   out1[n,j] = (A@W1)[n,j]
//   out2[n,j] = (A@W2)[n,j] + b2[j]
// Per k: 2 LDG + 4 LDS + 8 FMA = 1.75 instr/MAC.
template<int K>
__global__ void lin2_kernel(const float* __restrict__ a_ext, int a_id,
                            const float* __restrict__ W1,
                            const float* __restrict__ W2,
                            const float* __restrict__ b2,
                            int out1_id, int out2_id, int DO)
{
    __shared__ float sA[4 * K];
    const float* __restrict__ A = (a_id >= 0) ? scratch(a_id) : a_ext;
    float* __restrict__ out1 = scratch(out1_id);
    float* __restrict__ out2 = scratch(out2_id);

    int n0  = blockIdx.x * 4;
    int tid = threadIdx.x;
    int nt  = blockDim.x;

    for (int i = tid; i < 4 * K; i += nt) {
        int r = i / K, k = i - r * K;
        sA[i] = A[(size_t)(n0 + r) * K + k];
    }
    __syncthreads();

    int j = tid;
    if (j >= DO) return;

    float a10 = 0.f, a11 = 0.f, a12 = 0.f, a13 = 0.f;
    float a20 = 0.f, a21 = 0.f, a22 = 0.f, a23 = 0.f;
    #pragma unroll 4
    for (int k = 0; k < K; k++) {
        float w1 = W1[k * DO + j];
        float w2 = W2[k * DO + j];
        float s0 = sA[0 * K + k], s1 = sA[1 * K + k];
        float s2 = sA[2 * K + k], s3 = sA[3 * K + k];
        a10 += s0 * w1; a11 += s1 * w1; a12 += s2 * w1; a13 += s3 * w1;
        a20 += s0 * w2; a21 += s1 * w2; a22 += s2 * w2; a23 += s3 * w2;
    }

    float b = b2[j];
    out1[(size_t)(n0 + 0) * DO + j] = a10;
    out1[(size_t)(n0 + 1) * DO + j] = a11;
    out1[(size_t)(n0 + 2) * DO + j] = a12;
    out1[(size_t)(n0 + 3) * DO + j] = a13;
    out2[(size_t)(n0 + 0) * DO + j] = a20 + b;
    out2[(size_t)(n0 + 1) * DO + j] = a21 + b;
    out2[(size_t)(n0 + 2) * DO + j] = a22 + b;
    out2[(size_t)(n0 + 3) * DO + j] = a23 + b;
}

// ---------------------------------------------------------------------------
// Head: mu = agg3@Wlmu + h2@Wrmu + bmu ; lv = agg3@Wllv + h2@Wrlv + blv.
// 128 threads, 16 rows/block (ty = row group of 4, tx = column lane).
__global__ void head_kernel(const float* __restrict__ Wlmu,
                            const float* __restrict__ Wrmu,
                            const float* __restrict__ bmu,
                            const float* __restrict__ Wllv,
                            const float* __restrict__ Wrlv,
                            const float* __restrict__ blv,
                            float* __restrict__ out)
{
    __shared__ float sG[16 * D2];   // agg3 rows
    __shared__ float sH[16 * D2];   // h2 rows
    const float* __restrict__ G = scratch(6);
    const float* __restrict__ H = scratch(5);

    int n0  = blockIdx.x * 16;
    int tid = threadIdx.x;

    for (int i = tid; i < 16 * D2; i += 128) {
        int r = i / D2, k = i - r * D2;
        size_t idx = (size_t)(n0 + r) * D2 + k;
        sG[i] = G[idx];
        sH[i] = H[idx];
    }
    __syncthreads();

    int tx = tid & 31;
    int ty = tid >> 5;                 // 0..3 -> rows ty*4 .. ty*4+3
    if (tx >= DOUT) return;

    float mu0 = 0.f, mu1 = 0.f, mu2 = 0.f, mu3 = 0.f;
    float lv0 = 0.f, lv1 = 0.f, lv2 = 0.f, lv3 = 0.f;
    #pragma unroll 2
    for (int k = 0; k < D2; k++) {
        float wlm = Wlmu[k * DOUT + tx];
        float wrm = Wrmu[k * DOUT + tx];
        float wll = Wllv[k * DOUT + tx];
        float wrl = Wrlv[k * DOUT + tx];
        int base = (ty * 4) * D2 + k;
        float g0 = sG[base], g1 = sG[base + D2], g2 = sG[base + 2 * D2], g3 = sG[base + 3 * D2];
        float h0 = sH[base], h1 = sH[base + D2], h2v = sH[base + 2 * D2], h3 = sH[base + 3 * D2];
        mu0 += g0 * wlm + h0 * wrm;  mu1 += g1 * wlm + h1 * wrm;
        mu2 += g2 * wlm + h2v * wrm; mu3 += g3 * wlm + h3 * wrm;
        lv0 += g0 * wll + h0 * wrl;  lv1 += g1 * wll + h1 * wrl;
        lv2 += g2 * wll + h2v * wrl; lv3 += g3 * wll + h3 * wrl;
    }

    float bm = bmu[tx], bl = blv[tx];
    size_t lvoff = (size_t)NODES * DOUT;
    int row = n0 + ty * 4;
    out[(size_t)(row + 0) * DOUT + tx] = mu0 + bm;
    out[(size_t)(row + 1) * DOUT + tx] = mu1 + bm;
    out[(size_t)(row + 2) * DOUT + tx] = mu2 + bm;
    out[(size_t)(row + 3) * DOUT + tx] = mu3 + bm;
    out[lvoff + (size_t)(row + 0) * DOUT + tx] = lv0 + bl;
    out[lvoff + (size_t)(row + 1) * DOUT + tx] = lv1 + bl;
    out[lvoff + (size_t)(row + 2) * DOUT + tx] = lv2 + bl;
    out[lvoff + (size_t)(row + 3) * DOUT + tx] = lv3 + bl;
}

// ---------------------------------------------------------------------------
extern "C" void kernel_launch(void* const* d_in, const int* in_sizes, int n_in,
                              void* d_out, int out_size) {
    const float* x    = (const float*)d_in[0];
    const void*  ei   = (const void*)d_in[1];
    const float* Wl1  = (const float*)d_in[2];
    const float* Wr1  = (const float*)d_in[3];
    const float* b1   = (const float*)d_in[4];
    const float* Wl2  = (const float*)d_in[5];
    const float* Wr2  = (const float*)d_in[6];
    const float* b2   = (const float*)d_in[7];
    const float* Wlmu = (const float*)d_in[8];
    const float* Wrmu = (const float*)d_in[9];
    const float* bmu  = (const float*)d_in[10];
    const float* Wllv = (const float*)d_in[11];
    const float* Wrlv = (const float*)d_in[12];
    const float* blv  = (const float*)d_in[13];
    float* out = (float*)d_out;

    const int NB    = (NODES + 255) / 256;
    const int EB    = (ED + 255) / 256;
    const int LGRID = NODES / 4;              // 12500, exact

    // launches 0-4 (CSR build prefix)
    sniff_kernel<<<1, 32>>>(ei);
    init_kernel<<<NB, 256>>>();
    edge_prep_kernel<<<EB, 256>>>(ei);
    scan_local_kernel<<<NBLK, SCAN_B>>>();
    scan_blocksums_kernel<<<1, SCAN_B>>>();

    // launch 5 — the big fused layer-1 GEMM (hoisted here for ncu -s 5 -c 1):
    // (z1, xw1+b1) = x @ (Wl1, Wr1)     -> scratch 0, 2
    lin2_kernel<IN_D><<<LGRID, 128>>>(x, -1, Wl1, Wr1, b1, 0, 2, D1);

    // remaining CSR build
    scan_add_kernel<<<NB, 256>>>();
    scatter_kernel<<<EB, 256>>>();

    // agg1 = mean-gather(z1)            0 -> 1
    gather_kernel<<<NODES, 128>>>(0, 1, D1);

    // h1 = relu(xw1 + agg1)             in place in scratch 2
    add_relu_kernel<<<(NODES * D1 + 255) / 256, 256>>>(2, 1, NODES * D1);

    // (z2, hw2+b2) = h1 @ (Wl2, Wr2)    -> scratch 3, 5
    lin2_kernel<D1><<<LGRID, 128>>>(nullptr, 2, Wl2, Wr2, b2, 3, 5, D2);

    // agg2 = mean-gather(z2)            3 -> 4
    gather_kernel<<<NODES, 64>>>(3, 4, D2);

    // h2 = relu(hw2 + agg2)             in place in scratch 5
    add_relu_kernel<<<(NODES * D2 + 255) / 256, 256>>>(5, 4, NODES * D2);

    // agg3 = mean-gather(h2)            5 -> 6
    gather_kernel<<<NODES, 64>>>(5, 6, D2);

    // mu / lv heads (fused)             -> out
    head_kernel<<<NODES / 16, 128>>>(Wlmu, Wrmu, bmu, Wllv, Wrlv, blv, out);
}

// round 17
// speedup vs baseline: 1.4993x; 1.1112x over previous
#include <cuda_runtime.h>
#include <cstdint>

// ---------------------------------------------------------------------------
// GraphSAGE VGAE encoder, GB300.  R16: 8-row lin2, fused gather+relu, ILP.
//  * edge_index dtype sniffed at runtime (int32 vs int64)   [R13 fix]
//  * scratch resolved in-kernel via id switch               [R13 fix]
//  * GEMM pairs sharing A fused (dual-output lin2)          [R15 win]
// Dataflow:
//   (z1, xw1+b1) = x @ (Wl1, Wr1)
//   h1 = relu(xw1 + mean-gather(z1))     (fused gather_relu)
//   (z2, hw2+b2) = h1 @ (Wl2, Wr2)
//   h2 = relu(hw2 + mean-gather(z2))     (fused gather_relu)
//   agg3 = mean-gather(h2)
//   mu = agg3 @ Wlmu + h2 @ Wrmu + bmu ; lv likewise   (fused head)
// ---------------------------------------------------------------------------

static constexpr int NODES = 50000;
static constexpr int ED    = 800000;
static constexpr int IN_D  = 128;
static constexpr int D1    = 117;
static constexpr int D2    = 42;
static constexpr int DOUT  = 24;

static constexpr int SCAN_B = 256;
static constexpr int NBLK   = (NODES + SCAN_B - 1) / SCAN_B;   // 196

__device__ float g_z1  [NODES * D1];   // id 0
__device__ float g_agg1[NODES * D1];   // id 1 (unused now, kept for ids)
__device__ float g_h1  [NODES * D1];   // id 2  (xw1+b1, then h1 in place)
__device__ float g_z2  [NODES * D2];   // id 3
__device__ float g_agg2[NODES * D2];   // id 4 (unused now)
__device__ float g_h2  [NODES * D2];   // id 5  (hw2+b2, then h2 in place)
__device__ float g_agg3[NODES * D2];   // id 6
__device__ float g_invdeg[NODES];
__device__ int   g_is64;
__device__ int   g_src[ED];
__device__ int   g_dst[ED];
__device__ int   g_deg[NODES];
__device__ int   g_row_ptr[NODES + 1];
__device__ int   g_blocksum[NBLK];
__device__ int   g_blockoff[NBLK];
__device__ int   g_cursor[NODES];
__device__ int   g_csr_src[ED];

__device__ __forceinline__ float* scratch(int id) {
    switch (id) {
        case 0: return g_z1;
        case 1: return g_agg1;
        case 2: return g_h1;
        case 3: return g_z2;
        case 4: return g_agg2;
        case 5: return g_h2;
        case 6: return g_agg3;
    }
    return nullptr;
}

// ---------------------------------------------------------------------------
// sniff edge dtype (block 0) + zero degrees (all blocks).
__global__ void sniff_init_kernel(const void* __restrict__ ei) {
    int i = blockIdx.x * blockDim.x + threadIdx.x;
    if (i == 0) {
        const unsigned* w = (const unsigned*)ei;
        int zeros = 0;
        for (int t = 0; t < 256; t++) zeros += (w[2 * t + 1] == 0u) ? 1 : 0;
        g_is64 = (zeros >= 128) ? 1 : 0;
    }
    if (i < NODES) g_deg[i] = 0;
}

// decode edges -> g_src/g_dst, count in-degrees
__global__ void edge_prep_kernel(const void* __restrict__ ei) {
    int e = blockIdx.x * blockDim.x + threadIdx.x;
    if (e >= ED) return;
    int s, d;
    if (g_is64) {
        const long long* p = (const long long*)ei;
        s = (int)p[e];
        d = (int)p[ED + e];
    } else {
        const int* p = (const int*)ei;
        s = p[e];
        d = p[ED + e];
    }
    s = min(max(s, 0), NODES - 1);
    d = min(max(d, 0), NODES - 1);
    g_src[e] = s;
    g_dst[e] = d;
    atomicAdd(&g_deg[d], 1);
}

__global__ void scan_local_kernel() {
    __shared__ int sm[SCAN_B];
    int tid = threadIdx.x;
    int i = blockIdx.x * SCAN_B + tid;
    int v = (i < NODES) ? g_deg[i] : 0;
    sm[tid] = v;
    __syncthreads();
    for (int off = 1; off < SCAN_B; off <<= 1) {
        int t = (tid >= off) ? sm[tid - off] : 0;
        __syncthreads();
        sm[tid] += t;
        __syncthreads();
    }
    if (i < NODES) g_row_ptr[i] = sm[tid] - v;
    if (tid == SCAN_B - 1) g_blocksum[blockIdx.x] = sm[tid];
}

__global__ void scan_blocksums_kernel() {
    __shared__ int sm[SCAN_B];
    int tid = threadIdx.x;
    int v = (tid < NBLK) ? g_blocksum[tid] : 0;
    sm[tid] = v;
    __syncthreads();
    for (int off = 1; off < SCAN_B; off <<= 1) {
        int t = (tid >= off) ? sm[tid - off] : 0;
        __syncthreads();
        sm[tid] += t;
        __syncthreads();
    }
    if (tid < NBLK) g_blockoff[tid] = sm[tid] - v;
}

__global__ void scan_add_kernel() {
    int i = blockIdx.x * blockDim.x + threadIdx.x;
    if (i >= NODES) return;
    int rp = g_row_ptr[i] + g_blockoff[i / SCAN_B];
    g_row_ptr[i] = rp;
    g_cursor[i]  = rp;
    g_invdeg[i]  = 1.0f / fmaxf((float)g_deg[i], 1.0f);
    if (i == 0) g_row_ptr[NODES] = ED;
}

__global__ void scatter_kernel() {
    int e = blockIdx.x * blockDim.x + threadIdx.x;
    if (e >= ED) return;
    int pos = atomicAdd(&g_cursor[g_dst[e]], 1);
    g_csr_src[pos] = g_src[e];
}

// ---------------------------------------------------------------------------
// Fused mean-gather + residual + relu:
//   H[n,j] = relu( H[n,j] + invdeg[n] * sum_{e in N(n)} Z[src_e, j] )
// One block per node, lane j = column. Dual accumulators for MLP=2.
__global__ void gather_relu_kernel(int z_id, int h_id, int D) {
    const float* __restrict__ Z = scratch(z_id);
    float*       __restrict__ H = scratch(h_id);
    int n = blockIdx.x;
    int j = threadIdx.x;
    if (j >= D) return;
    int beg = g_row_ptr[n];
    int end = g_row_ptr[n + 1];
    float acc0 = 0.0f, acc1 = 0.0f;
    int i = beg;
    for (; i + 1 < end; i += 2) {
        int s0 = g_csr_src[i];
        int s1 = g_csr_src[i + 1];
        acc0 += Z[(size_t)s0 * D + j];
        acc1 += Z[(size_t)s1 * D + j];
    }
    if (i < end) acc0 += Z[(size_t)g_csr_src[i] * D + j];
    size_t idx = (size_t)n * D + j;
    H[idx] = fmaxf(H[idx] + (acc0 + acc1) * g_invdeg[n], 0.0f);
}

// Plain mean-gather (for agg3): AGG[n,j] = invdeg[n] * sum Z[src,j]
__global__ void gather_kernel(int z_id, int agg_id, int D) {
    const float* __restrict__ Z   = scratch(z_id);
    float*       __restrict__ AGG = scratch(agg_id);
    int n = blockIdx.x;
    int j = threadIdx.x;
    if (j >= D) return;
    int beg = g_row_ptr[n];
    int end = g_row_ptr[n + 1];
    float acc0 = 0.0f, acc1 = 0.0f;
    int i = beg;
    for (; i + 1 < end; i += 2) {
        int s0 = g_csr_src[i];
        int s1 = g_csr_src[i + 1];
        acc0 += Z[(size_t)s0 * D + j];
        acc1 += Z[(size_t)s1 * D + j];
    }
    if (i < end) acc0 += Z[(size_t)g_csr_src[i] * D + j];
    AGG[(size_t)n * D + j] = (acc0 + acc1) * g_invdeg[n];
}

// ---------------------------------------------------------------------------
// Fused dual-output linear, 8 rows/block (128 threads, thread j = column):
//   out1[n,j] = (A@W1)[n,j]
//   out2[n,j] = (A@W2)[n,j] + b2[j]
// Per k: 2 LDG + 8 LDS + 16 FMA  ->  1.625 instr/MAC, half the W reloads of
// the 4-row version, occupancy unchanged (4 KB smem, grid 6250).
template<int K>
__global__ void lin2_kernel(const float* __restrict__ a_ext, int a_id,
                            const float* __restrict__ W1,
                            const float* __restrict__ W2,
                            const float* __restrict__ b2,
                            int out1_id, int out2_id, int DO)
{
    __shared__ float sA[8 * K];
    const float* __restrict__ A = (a_id >= 0) ? scratch(a_id) : a_ext;
    float* __restrict__ out1 = scratch(out1_id);
    float* __restrict__ out2 = scratch(out2_id);

    int n0  = blockIdx.x * 8;
    int tid = threadIdx.x;

    for (int i = tid; i < 8 * K; i += 128) {
        int r = i / K, k = i - r * K;
        sA[i] = A[(size_t)(n0 + r) * K + k];
    }
    __syncthreads();

    int j = tid;
    if (j >= DO) return;

    float a1[8], a2[8];
    #pragma unroll
    for (int r = 0; r < 8; r++) { a1[r] = 0.f; a2[r] = 0.f; }

    #pragma unroll 4
    for (int k = 0; k < K; k++) {
        float w1 = W1[k * DO + j];
        float w2 = W2[k * DO + j];
        #pragma unroll
        for (int r = 0; r < 8; r++) {
            float s = sA[r * K + k];
            a1[r] += s * w1;
            a2[r] += s * w2;
        }
    }

    float b = b2[j];
    #pragma unroll
    for (int r = 0; r < 8; r++) {
        out1[(size_t)(n0 + r) * DO + j] = a1[r];
        out2[(size_t)(n0 + r) * DO + j] = a2[r] + b;
    }
}

// ---------------------------------------------------------------------------
// Head: mu = agg3@Wlmu + h2@Wrmu + bmu ; lv = agg3@Wllv + h2@Wrlv + blv.
// 128 threads, 16 rows/block (ty = row group of 4, tx = column lane).
__global__ void head_kernel(const float* __restrict__ Wlmu,
                            const float* __restrict__ Wrmu,
                            const float* __restrict__ bmu,
                            const float* __restrict__ Wllv,
                            const float* __restrict__ Wrlv,
                            const float* __restrict__ blv,
                            float* __restrict__ out)
{
    __shared__ float sG[16 * D2];
    __shared__ float sH[16 * D2];
    const float* __restrict__ G = scratch(6);
    const float* __restrict__ H = scratch(5);

    int n0  = blockIdx.x * 16;
    int tid = threadIdx.x;

    for (int i = tid; i < 16 * D2; i += 128) {
        int r = i / D2, k = i - r * D2;
        size_t idx = (size_t)(n0 + r) * D2 + k;
        sG[i] = G[idx];
        sH[i] = H[idx];
    }
    __syncthreads();

    int tx = tid & 31;
    int ty = tid >> 5;
    if (tx >= DOUT) return;

    float mu0 = 0.f, mu1 = 0.f, mu2 = 0.f, mu3 = 0.f;
    float lv0 = 0.f, lv1 = 0.f, lv2 = 0.f, lv3 = 0.f;
    #pragma unroll 2
    for (int k = 0; k < D2; k++) {
        float wlm = Wlmu[k * DOUT + tx];
        float wrm = Wrmu[k * DOUT + tx];
        float wll = Wllv[k * DOUT + tx];
        float wrl = Wrlv[k * DOUT + tx];
        int base = (ty * 4) * D2 + k;
        float g0 = sG[base], g1 = sG[base + D2], g2 = sG[base + 2 * D2], g3 = sG[base + 3 * D2];
        float h0 = sH[base], h1 = sH[base + D2], h2v = sH[base + 2 * D2], h3 = sH[base + 3 * D2];
        mu0 += g0 * wlm + h0 * wrm;  mu1 += g1 * wlm + h1 * wrm;
        mu2 += g2 * wlm + h2v * wrm; mu3 += g3 * wlm + h3 * wrm;
        lv0 += g0 * wll + h0 * wrl;  lv1 += g1 * wll + h1 * wrl;
        lv2 += g2 * wll + h2v * wrl; lv3 += g3 * wll + h3 * wrl;
    }

    float bm = bmu[tx], bl = blv[tx];
    size_t lvoff = (size_t)NODES * DOUT;
    int row = n0 + ty * 4;
    out[(size_t)(row + 0) * DOUT + tx] = mu0 + bm;
    out[(size_t)(row + 1) * DOUT + tx] = mu1 + bm;
    out[(size_t)(row + 2) * DOUT + tx] = mu2 + bm;
    out[(size_t)(row + 3) * DOUT + tx] = mu3 + bm;
    out[lvoff + (size_t)(row + 0) * DOUT + tx] = lv0 + bl;
    out[lvoff + (size_t)(row + 1) * DOUT + tx] = lv1 + bl;
    out[lvoff + (size_t)(row + 2) * DOUT + tx] = lv2 + bl;
    out[lvoff + (size_t)(row + 3) * DOUT + tx] = lv3 + bl;
}

// ---------------------------------------------------------------------------
extern "C" void kernel_launch(void* const* d_in, const int* in_sizes, int n_in,
                              void* d_out, int out_size) {
    const float* x    = (const float*)d_in[0];
    const void*  ei   = (const void*)d_in[1];
    const float* Wl1  = (const float*)d_in[2];
    const float* Wr1  = (const float*)d_in[3];
    const float* b1   = (const float*)d_in[4];
    const float* Wl2  = (const float*)d_in[5];
    const float* Wr2  = (const float*)d_in[6];
    const float* b2   = (const float*)d_in[7];
    const float* Wlmu = (const float*)d_in[8];
    const float* Wrmu = (const float*)d_in[9];
    const float* bmu  = (const float*)d_in[10];
    const float* Wllv = (const float*)d_in[11];
    const float* Wrlv = (const float*)d_in[12];
    const float* blv  = (const float*)d_in[13];
    float* out = (float*)d_out;

    const int NB    = (NODES + 255) / 256;
    const int EB    = (ED + 255) / 256;
    const int LGRID = NODES / 8;              // 6250, exact

    // ---- CSR build ----
    sniff_init_kernel<<<NB, 256>>>(ei);
    edge_prep_kernel<<<EB, 256>>>(ei);
    scan_local_kernel<<<NBLK, SCAN_B>>>();
    scan_blocksums_kernel<<<1, SCAN_B>>>();
    scan_add_kernel<<<NB, 256>>>();

    // (z1, xw1+b1) = x @ (Wl1, Wr1)    -> scratch 0, 2   (independent of CSR)
    lin2_kernel<IN_D><<<LGRID, 128>>>(x, -1, Wl1, Wr1, b1, 0, 2, D1);

    scatter_kernel<<<EB, 256>>>();

    // h1 = relu(xw1 + mean-gather(z1))  in place in scratch 2
    gather_relu_kernel<<<NODES, 128>>>(0, 2, D1);

    // (z2, hw2+b2) = h1 @ (Wl2, Wr2)   -> scratch 3, 5
    lin2_kernel<D1><<<LGRID, 128>>>(nullptr, 2, Wl2, Wr2, b2, 3, 5, D2);

    // h2 = relu(hw2 + mean-gather(z2))  in place in scratch 5
    gather_relu_kernel<<<NODES, 64>>>(3, 5, D2);

    // agg3 = mean-gather(h2)            5 -> 6
    gather_kernel<<<NODES, 64>>>(5, 6, D2);

    // mu / lv heads (fused)             -> out
    head_kernel<<<NODES / 16, 128>>>(Wlmu, Wrmu, bmu, Wllv, Wrlv, blv, out);
}